// round 15
// baseline (speedup 1.0000x reference)
#include <cuda_runtime.h>
#include <cuda_fp16.h>
#include <cstdint>

// SkelConv v15: v14 with the block addressing fixed (1-row stride, not 8).
// Conv1d(K=15) = 15 tap-shifted GEMMs: D[m,co] += sum_ci A[m+tap,ci]*B_tap[ci,co]
// A = fp16(x) single pass; B = fp16 hi+lo (D = A*Bh + A*Bl).
// m16n8k16: A-frag for tap t = 8-row blocks starting at rows {t, t+8};
// blocks at consecutive row starts loaded via ldmatrix.x2, rolling window.

#define C_IN   103
#define C_OUT  206
#define KK     15
#define TLEN   8192
#define NB     32
#define TPB    128
#define CTAT   256          // time per CTA: 4 warps * 4 mtiles * 16
#define NROW   272          // 256 + halo
#define RST    24           // row stride in fp16 elems (48 B)

// y = 0..25: 0,1 = root halves (7 out ch each), y>=2 -> joint j=y-1 (8 out ch)
__device__ __forceinline__ void jp(int y, int& i0, int& iw, int& o0, int& ow) {
    if (y == 0)      { i0 = 0;  iw = 11; o0 = 0; ow = 7; }
    else if (y == 1) { i0 = 0;  iw = 11; o0 = 7; ow = 7; }
    else {
        const int j = y - 1;
        o0 = 14 + (j - 1) * 8; ow = 8;
        if (j == 1)       { i0 = 0;              iw = 15; }
        else if (j == 24) { i0 = 95;             iw = 8;  }
        else              { i0 = 7 + (j - 2) * 4; iw = 12; }
    }
}

__device__ __forceinline__ uint32_t s2u(const void* p) {
    uint32_t a;
    asm("{ .reg .u64 t; cvta.to.shared.u64 t, %1; cvt.u32.u64 %0, t; }"
        : "=r"(a) : "l"(p));
    return a;
}

// Load one 8-row x 16-ci block as two 8x8 b16 matrices (ci 0-7, ci 8-15).
__device__ __forceinline__ void ldmat2(uint32_t& r0, uint32_t& r1, uint32_t addr) {
    asm volatile("ldmatrix.sync.aligned.m8n8.x2.shared.b16 {%0,%1}, [%2];"
                 : "=r"(r0), "=r"(r1) : "r"(addr));
}

__device__ __forceinline__ void mma16816(float& d0, float& d1, float& d2, float& d3,
                                         uint32_t a0, uint32_t a1, uint32_t a2,
                                         uint32_t a3, uint32_t b0, uint32_t b1) {
    asm volatile(
        "mma.sync.aligned.m16n8k16.row.col.f32.f16.f16.f32 "
        "{%0,%1,%2,%3}, {%4,%5,%6,%7}, {%8,%9}, {%0,%1,%2,%3};"
        : "+f"(d0), "+f"(d1), "+f"(d2), "+f"(d3)
        : "r"(a0), "r"(a1), "r"(a2), "r"(a3), "r"(b0), "r"(b1));
}

__device__ __forceinline__ uint32_t pkhf2(float lo, float hi) {
    __half l = __float2half(lo);
    __half h = __float2half(hi);
    uint16_t lu = *reinterpret_cast<uint16_t*>(&l);
    uint16_t hu = *reinterpret_cast<uint16_t*>(&h);
    return (uint32_t)lu | ((uint32_t)hu << 16);
}

__global__ void __launch_bounds__(TPB, 4)
skel_hmma3_kernel(const float* __restrict__ x,
                  const float* __restrict__ w,
                  const float* __restrict__ bias,
                  const float* __restrict__ mask,
                  float* __restrict__ out)
{
    int i0, iw, o0, ow;
    jp(blockIdx.y, i0, iw, o0, ow);

    const int b     = blockIdx.z;
    const int tile0 = blockIdx.x * CTAT;
    const int tid   = threadIdx.x;
    const int wid   = tid >> 5;
    const int lane  = tid & 31;

    __shared__ __half xsh[NROW * RST];        // 13056 B
    __shared__ uint32_t bsh[KK * 64];         // 3840 B  (fp16 hi frags)
    __shared__ uint32_t bsl[KK * 64];         // 3840 B  (fp16 lo frags)

    // ---- stage x as fp16 (single pass), coalesced per-ci rows ----
    for (int ci = 0; ci < 16; ci++) {
        const float* xrow = x + ((size_t)b * C_IN + (i0 + ci)) * TLEN;
        const bool civ = (ci < iw);
        for (int r = tid; r < NROW; r += TPB) {
            const int t = tile0 - 7 + r;
            float v = (civ && t >= 0 && t < TLEN) ? xrow[t] : 0.0f;
            xsh[r * RST + ci] = __float2half(v);
        }
    }
    // ---- stage masked weights as fp16 hi/lo B fragments ----
    for (int idx = tid; idx < KK * 64; idx += TPB) {
        const int tap = idx >> 6;
        const int kp  = (idx >> 3) & 7;
        const int co  = idx & 7;
        float v0 = 0.0f, v1 = 0.0f;
        if (co < ow) {
            const int ci0 = 2 * kp, ci1 = 2 * kp + 1;
            if (ci0 < iw) {
                const int gi = ((o0 + co) * C_IN + (i0 + ci0)) * KK + tap;
                v0 = w[gi] * mask[gi];
            }
            if (ci1 < iw) {
                const int gi = ((o0 + co) * C_IN + (i0 + ci1)) * KK + tap;
                v1 = w[gi] * mask[gi];
            }
        }
        __half h0 = __float2half(v0);
        __half h1 = __float2half(v1);
        bsh[idx] = pkhf2(__half2float(h0), __half2float(h1));
        bsl[idx] = pkhf2(v0 - __half2float(h0), v1 - __half2float(h1));
    }
    __syncthreads();

    // ---- per-lane B fragment registers (held across M-loop) ----
    const int gid = lane >> 2;      // 0..7  (n index)
    const int tig = lane & 3;       // 0..3  (k pair index)
    uint32_t bh0[KK], bh1[KK], bl0[KK], bl1[KK];
#pragma unroll
    for (int tap = 0; tap < KK; tap++) {
        const int base = tap * 64 + tig * 8 + gid;
        bh0[tap] = bsh[base];
        bh1[tap] = bsh[base + 32];
        bl0[tap] = bsl[base];
        bl1[tap] = bsl[base + 32];
    }

    // ldmatrix.x2 lane address: lanes 0..7 -> matrix 0 rows (ci 0-7),
    // lanes 8..15 -> matrix 1 rows (+16B, ci 8-15).
    const int l16    = lane & 15;
    const int rowoff = l16 & 7;
    const int coloff = (l16 >> 3) << 4;
    const uint32_t a_base = s2u(xsh) + (uint32_t)(rowoff * 48 + coloff);

    const float bias0 = (2 * tig < ow)     ? bias[o0 + 2 * tig]     : 0.0f;
    const float bias1 = (2 * tig + 1 < ow) ? bias[o0 + 2 * tig + 1] : 0.0f;
    float* ob = out + (size_t)b * C_OUT * TLEN;

#pragma unroll
    for (int mt = 0; mt < 4; mt++) {
        const int rbase = (wid * 4 + mt) * 16;
        const int T0    = tile0 + rbase;
        float d0 = 0.0f, d1 = 0.0f, d2 = 0.0f, d3 = 0.0f;

        const uint32_t ab = a_base + (uint32_t)(rbase * 48);

        // blk[s] = 8 rows starting at row rbase+s (1-row stride!), s = 0..22.
        // Rolling: preload s=0..7, load s=tap+8 inside the tap loop.
        uint32_t blk[23][2];
#pragma unroll
        for (int s = 0; s < 8; s++) ldmat2(blk[s][0], blk[s][1], ab + s * 48);

#pragma unroll
        for (int tap = 0; tap < KK; tap++) {
            ldmat2(blk[tap + 8][0], blk[tap + 8][1], ab + (tap + 8) * 48);
            // A frag for tap: rows {tap..tap+7} = blk[tap], rows {tap+8..tap+15}
            // = blk[tap+8]; a0/a2 = ci 0-7 / 8-15 of blk[tap], a1/a3 of blk[tap+8].
            mma16816(d0, d1, d2, d3,
                     blk[tap][0], blk[tap + 8][0], blk[tap][1], blk[tap + 8][1],
                     bh0[tap], bh1[tap]);
            mma16816(d0, d1, d2, d3,
                     blk[tap][0], blk[tap + 8][0], blk[tap][1], blk[tap + 8][1],
                     bl0[tap], bl1[tap]);
        }

        // D mapping: d0=(row gid, n=2tig), d1=(gid, 2tig+1),
        //            d2=(gid+8, 2tig), d3=(gid+8, 2tig+1)
        const int t0r = T0 + gid;
        if (2 * tig < ow) {
            float* p = ob + (size_t)(o0 + 2 * tig) * TLEN;
            p[t0r]     = d0 + bias0;
            p[t0r + 8] = d2 + bias0;
        }
        if (2 * tig + 1 < ow) {
            float* p = ob + (size_t)(o0 + 2 * tig + 1) * TLEN;
            p[t0r]     = d1 + bias1;
            p[t0r + 8] = d3 + bias1;
        }
    }
}

extern "C" void kernel_launch(void* const* d_in, const int* in_sizes, int n_in,
                              void* d_out, int out_size)
{
    (void)in_sizes; (void)n_in; (void)out_size;
    const float* x    = (const float*)d_in[0];
    const float* w    = (const float*)d_in[1];
    const float* bias = (const float*)d_in[2];
    const float* mask = (const float*)d_in[3];
    float* out = (float*)d_out;

    dim3 grid(TLEN / CTAT, 26, NB);
    skel_hmma3_kernel<<<grid, TPB>>>(x, w, bias, mask, out);
}

// round 16
// speedup vs baseline: 1.0614x; 1.0614x over previous
#include <cuda_runtime.h>
#include <cuda_fp16.h>
#include <cstdint>

// SkelConv v16: fp16 HMMA, single-precision-split-free (A fp16, B fp16),
// 15 MMAs per mtile, mtiles processed in PAIRS -> 2 independent accumulator
// chains per warp (breaks the serial HMMA RAW chain that bound v15).
// Conv1d(K=15) = 15 tap-shifted GEMMs; A-frag for tap t = 8-row blocks at
// rows {t, t+8}, rolling ldmatrix.x2 window per mtile.

#define C_IN   103
#define C_OUT  206
#define KK     15
#define TLEN   8192
#define NB     32
#define TPB    128
#define CTAT   256          // time per CTA: 4 warps * 4 mtiles * 16
#define NROW   272          // 256 + halo
#define RST    24           // row stride in fp16 elems (48 B)

// y = 0..25: 0,1 = root halves (7 out ch each), y>=2 -> joint j=y-1 (8 out ch)
__device__ __forceinline__ void jp(int y, int& i0, int& iw, int& o0, int& ow) {
    if (y == 0)      { i0 = 0;  iw = 11; o0 = 0; ow = 7; }
    else if (y == 1) { i0 = 0;  iw = 11; o0 = 7; ow = 7; }
    else {
        const int j = y - 1;
        o0 = 14 + (j - 1) * 8; ow = 8;
        if (j == 1)       { i0 = 0;              iw = 15; }
        else if (j == 24) { i0 = 95;             iw = 8;  }
        else              { i0 = 7 + (j - 2) * 4; iw = 12; }
    }
}

__device__ __forceinline__ uint32_t s2u(const void* p) {
    uint32_t a;
    asm("{ .reg .u64 t; cvta.to.shared.u64 t, %1; cvt.u32.u64 %0, t; }"
        : "=r"(a) : "l"(p));
    return a;
}

__device__ __forceinline__ void ldmat2(uint32_t& r0, uint32_t& r1, uint32_t addr) {
    asm volatile("ldmatrix.sync.aligned.m8n8.x2.shared.b16 {%0,%1}, [%2];"
                 : "=r"(r0), "=r"(r1) : "r"(addr));
}

__device__ __forceinline__ void mma16816(float& d0, float& d1, float& d2, float& d3,
                                         uint32_t a0, uint32_t a1, uint32_t a2,
                                         uint32_t a3, uint32_t b0, uint32_t b1) {
    asm volatile(
        "mma.sync.aligned.m16n8k16.row.col.f32.f16.f16.f32 "
        "{%0,%1,%2,%3}, {%4,%5,%6,%7}, {%8,%9}, {%0,%1,%2,%3};"
        : "+f"(d0), "+f"(d1), "+f"(d2), "+f"(d3)
        : "r"(a0), "r"(a1), "r"(a2), "r"(a3), "r"(b0), "r"(b1));
}

__device__ __forceinline__ uint32_t pkhf2(float lo, float hi) {
    __half l = __float2half(lo);
    __half h = __float2half(hi);
    uint16_t lu = *reinterpret_cast<uint16_t*>(&l);
    uint16_t hu = *reinterpret_cast<uint16_t*>(&h);
    return (uint32_t)lu | ((uint32_t)hu << 16);
}

__global__ void __launch_bounds__(TPB, 4)
skel_hmma4_kernel(const float* __restrict__ x,
                  const float* __restrict__ w,
                  const float* __restrict__ bias,
                  const float* __restrict__ mask,
                  float* __restrict__ out)
{
    int i0, iw, o0, ow;
    jp(blockIdx.y, i0, iw, o0, ow);

    const int b     = blockIdx.z;
    const int tile0 = blockIdx.x * CTAT;
    const int tid   = threadIdx.x;
    const int wid   = tid >> 5;
    const int lane  = tid & 31;

    __shared__ __half xsh[NROW * RST];        // 13056 B
    __shared__ uint32_t bsh[KK * 64];         // 3840 B  (fp16 B frags)

    // ---- stage x as fp16, coalesced per-ci rows ----
    for (int ci = 0; ci < 16; ci++) {
        const float* xrow = x + ((size_t)b * C_IN + (i0 + ci)) * TLEN;
        const bool civ = (ci < iw);
        for (int r = tid; r < NROW; r += TPB) {
            const int t = tile0 - 7 + r;
            float v = (civ && t >= 0 && t < TLEN) ? xrow[t] : 0.0f;
            xsh[r * RST + ci] = __float2half(v);
        }
    }
    // ---- stage masked weights as fp16 B fragments ----
    for (int idx = tid; idx < KK * 64; idx += TPB) {
        const int tap = idx >> 6;
        const int kp  = (idx >> 3) & 7;
        const int co  = idx & 7;
        float v0 = 0.0f, v1 = 0.0f;
        if (co < ow) {
            const int ci0 = 2 * kp, ci1 = 2 * kp + 1;
            if (ci0 < iw) {
                const int gi = ((o0 + co) * C_IN + (i0 + ci0)) * KK + tap;
                v0 = w[gi] * mask[gi];
            }
            if (ci1 < iw) {
                const int gi = ((o0 + co) * C_IN + (i0 + ci1)) * KK + tap;
                v1 = w[gi] * mask[gi];
            }
        }
        bsh[idx] = pkhf2(v0, v1);
    }
    __syncthreads();

    // ---- per-lane B fragment registers (held across all mtiles) ----
    const int gid = lane >> 2;      // 0..7  (n index)
    const int tig = lane & 3;       // 0..3  (k pair index)
    uint32_t bh0[KK], bh1[KK];
#pragma unroll
    for (int tap = 0; tap < KK; tap++) {
        const int base = tap * 64 + tig * 8 + gid;
        bh0[tap] = bsh[base];
        bh1[tap] = bsh[base + 32];
    }

    // ldmatrix.x2 lane address: lanes 0..7 -> matrix 0 (ci 0-7),
    // lanes 8..15 -> matrix 1 (+16B, ci 8-15).
    const int l16    = lane & 15;
    const int rowoff = l16 & 7;
    const int coloff = (l16 >> 3) << 4;
    const uint32_t a_base = s2u(xsh) + (uint32_t)(rowoff * 48 + coloff);

    const float bias0 = (2 * tig < ow)     ? bias[o0 + 2 * tig]     : 0.0f;
    const float bias1 = (2 * tig + 1 < ow) ? bias[o0 + 2 * tig + 1] : 0.0f;
    float* ob = out + (size_t)b * C_OUT * TLEN;

#pragma unroll
    for (int mtp = 0; mtp < 2; mtp++) {
        const int rb0 = (wid * 4 + 2 * mtp) * 16;
        const int rb1 = rb0 + 16;
        float dA0 = 0.f, dA1 = 0.f, dA2 = 0.f, dA3 = 0.f;
        float dB0 = 0.f, dB1 = 0.f, dB2 = 0.f, dB3 = 0.f;

        const uint32_t abA = a_base + (uint32_t)(rb0 * 48);
        const uint32_t abB = a_base + (uint32_t)(rb1 * 48);

        // Rolling 1-row-stride blocks per mtile: blk[s] = rows rb+s..rb+s+7.
        uint32_t blkA[23][2], blkB[23][2];
#pragma unroll
        for (int s = 0; s < 8; s++) {
            ldmat2(blkA[s][0], blkA[s][1], abA + s * 48);
            ldmat2(blkB[s][0], blkB[s][1], abB + s * 48);
        }

#pragma unroll
        for (int tap = 0; tap < KK; tap++) {
            ldmat2(blkA[tap + 8][0], blkA[tap + 8][1], abA + (tap + 8) * 48);
            ldmat2(blkB[tap + 8][0], blkB[tap + 8][1], abB + (tap + 8) * 48);
            mma16816(dA0, dA1, dA2, dA3,
                     blkA[tap][0], blkA[tap + 8][0], blkA[tap][1], blkA[tap + 8][1],
                     bh0[tap], bh1[tap]);
            mma16816(dB0, dB1, dB2, dB3,
                     blkB[tap][0], blkB[tap + 8][0], blkB[tap][1], blkB[tap + 8][1],
                     bh0[tap], bh1[tap]);
        }

        // D mapping: d0=(row gid, n=2tig), d1=(gid, 2tig+1),
        //            d2=(gid+8, 2tig), d3=(gid+8, 2tig+1)
        const int tA = tile0 + rb0 + gid;
        const int tB = tile0 + rb1 + gid;
        if (2 * tig < ow) {
            float* p = ob + (size_t)(o0 + 2 * tig) * TLEN;
            p[tA]     = dA0 + bias0;
            p[tA + 8] = dA2 + bias0;
            p[tB]     = dB0 + bias0;
            p[tB + 8] = dB2 + bias0;
        }
        if (2 * tig + 1 < ow) {
            float* p = ob + (size_t)(o0 + 2 * tig + 1) * TLEN;
            p[tA]     = dA1 + bias1;
            p[tA + 8] = dA3 + bias1;
            p[tB]     = dB1 + bias1;
            p[tB + 8] = dB3 + bias1;
        }
    }
}

extern "C" void kernel_launch(void* const* d_in, const int* in_sizes, int n_in,
                              void* d_out, int out_size)
{
    (void)in_sizes; (void)n_in; (void)out_size;
    const float* x    = (const float*)d_in[0];
    const float* w    = (const float*)d_in[1];
    const float* bias = (const float*)d_in[2];
    const float* mask = (const float*)d_in[3];
    float* out = (float*)d_out;

    dim3 grid(TLEN / CTAT, 26, NB);
    skel_hmma4_kernel<<<grid, TPB>>>(x, w, bias, mask, out);
}

// round 17
// speedup vs baseline: 1.5417x; 1.4525x over previous
#include <cuda_runtime.h>
#include <cuda_fp16.h>
#include <cstdint>

// SkelConv v17: fp16 HMMA; per mtile ALL 23 A-blocks preloaded (no load->use
// adjacency), 4 independent accumulator chains (taps mod 4), aligned float4
// staging. Conv1d(K=15) = 15 tap-shifted GEMMs, m16n8k16.
// Tile rows: r = t - (tile0-8); A-frag for tap k of mtile rbase = blocks
// {k, k+8} starting at row rbase+1+k.

#define C_IN   103
#define C_OUT  206
#define KK     15
#define TLEN   8192
#define NB     32
#define TPB    128
#define CTAT   256          // 4 warps * 4 mtiles * 16
#define NROW   272
#define RST    24           // fp16 row stride (48 B)

// y = 0..25: 0,1 = root halves (7 out ch each), y>=2 -> joint j=y-1 (8 out ch)
__device__ __forceinline__ void jp(int y, int& i0, int& iw, int& o0, int& ow) {
    if (y == 0)      { i0 = 0;  iw = 11; o0 = 0; ow = 7; }
    else if (y == 1) { i0 = 0;  iw = 11; o0 = 7; ow = 7; }
    else {
        const int j = y - 1;
        o0 = 14 + (j - 1) * 8; ow = 8;
        if (j == 1)       { i0 = 0;              iw = 15; }
        else if (j == 24) { i0 = 95;             iw = 8;  }
        else              { i0 = 7 + (j - 2) * 4; iw = 12; }
    }
}

__device__ __forceinline__ uint32_t s2u(const void* p) {
    uint32_t a;
    asm("{ .reg .u64 t; cvta.to.shared.u64 t, %1; cvt.u32.u64 %0, t; }"
        : "=r"(a) : "l"(p));
    return a;
}

__device__ __forceinline__ void ldmat2(uint32_t& r0, uint32_t& r1, uint32_t addr) {
    asm volatile("ldmatrix.sync.aligned.m8n8.x2.shared.b16 {%0,%1}, [%2];"
                 : "=r"(r0), "=r"(r1) : "r"(addr));
}

__device__ __forceinline__ void mma16816(float& d0, float& d1, float& d2, float& d3,
                                         uint32_t a0, uint32_t a1, uint32_t a2,
                                         uint32_t a3, uint32_t b0, uint32_t b1) {
    asm volatile(
        "mma.sync.aligned.m16n8k16.row.col.f32.f16.f16.f32 "
        "{%0,%1,%2,%3}, {%4,%5,%6,%7}, {%8,%9}, {%0,%1,%2,%3};"
        : "+f"(d0), "+f"(d1), "+f"(d2), "+f"(d3)
        : "r"(a0), "r"(a1), "r"(a2), "r"(a3), "r"(b0), "r"(b1));
}

__device__ __forceinline__ uint32_t pkhf2(float lo, float hi) {
    __half2 h = __floats2half2_rn(lo, hi);
    return *reinterpret_cast<uint32_t*>(&h);
}

__global__ void __launch_bounds__(TPB, 4)
skel_hmma5_kernel(const float* __restrict__ x,
                  const float* __restrict__ w,
                  const float* __restrict__ bias,
                  const float* __restrict__ mask,
                  float* __restrict__ out)
{
    int i0, iw, o0, ow;
    jp(blockIdx.y, i0, iw, o0, ow);

    const int b     = blockIdx.z;
    const int tile0 = blockIdx.x * CTAT;
    const int tid   = threadIdx.x;
    const int wid   = tid >> 5;
    const int lane  = tid & 31;

    __shared__ __half xsh[NROW * RST];        // 13056 B
    __shared__ uint32_t bsh[KK * 64];         // 3840 B

    // ---- stage x as fp16: row r <-> t = tile0-8+r, aligned float4 loads ----
    {
        const int t0 = tile0 - 8;
        const bool interior = (t0 >= 0) && (t0 + NROW <= TLEN);
        for (int idx = tid; idx < 16 * (NROW / 4); idx += TPB) {
            const int ci = idx / (NROW / 4);
            const int m  = idx - ci * (NROW / 4);
            const int r  = 4 * m;
            const float* xrow = x + ((size_t)b * C_IN + (i0 + ci)) * TLEN;
            float4 v;
            if (ci < iw && interior) {
                v = *reinterpret_cast<const float4*>(xrow + t0 + r);
            } else if (ci < iw) {
                const int t = t0 + r;
                v.x = (t + 0 >= 0 && t + 0 < TLEN) ? xrow[t + 0] : 0.0f;
                v.y = (t + 1 >= 0 && t + 1 < TLEN) ? xrow[t + 1] : 0.0f;
                v.z = (t + 2 >= 0 && t + 2 < TLEN) ? xrow[t + 2] : 0.0f;
                v.w = (t + 3 >= 0 && t + 3 < TLEN) ? xrow[t + 3] : 0.0f;
            } else {
                v = make_float4(0.f, 0.f, 0.f, 0.f);
            }
            xsh[(r + 0) * RST + ci] = __float2half(v.x);
            xsh[(r + 1) * RST + ci] = __float2half(v.y);
            xsh[(r + 2) * RST + ci] = __float2half(v.z);
            xsh[(r + 3) * RST + ci] = __float2half(v.w);
        }
    }
    // ---- stage masked weights as fp16 B fragments ----
    for (int idx = tid; idx < KK * 64; idx += TPB) {
        const int tap = idx >> 6;
        const int kp  = (idx >> 3) & 7;
        const int co  = idx & 7;
        float v0 = 0.0f, v1 = 0.0f;
        if (co < ow) {
            const int ci0 = 2 * kp, ci1 = 2 * kp + 1;
            if (ci0 < iw) {
                const int gi = ((o0 + co) * C_IN + (i0 + ci0)) * KK + tap;
                v0 = w[gi] * mask[gi];
            }
            if (ci1 < iw) {
                const int gi = ((o0 + co) * C_IN + (i0 + ci1)) * KK + tap;
                v1 = w[gi] * mask[gi];
            }
        }
        bsh[idx] = pkhf2(v0, v1);
    }
    __syncthreads();

    // ---- per-lane B fragment registers ----
    const int gid = lane >> 2;      // n index 0..7
    const int tig = lane & 3;       // k-pair index 0..3
    uint32_t bh0[KK], bh1[KK];
#pragma unroll
    for (int tap = 0; tap < KK; tap++) {
        const int base = tap * 64 + tig * 8 + gid;
        bh0[tap] = bsh[base];
        bh1[tap] = bsh[base + 32];
    }

    // ldmatrix.x2 lane addressing (lanes 0..7 -> ci 0-7, 8..15 -> ci 8-15)
    const int l16    = lane & 15;
    const int rowoff = l16 & 7;
    const int coloff = (l16 >> 3) << 4;
    const uint32_t a_base = s2u(xsh) + (uint32_t)(rowoff * 48 + coloff);

    const float bias0 = (2 * tig < ow)     ? bias[o0 + 2 * tig]     : 0.0f;
    const float bias1 = (2 * tig + 1 < ow) ? bias[o0 + 2 * tig + 1] : 0.0f;
    float* ob = out + (size_t)b * C_OUT * TLEN;

#pragma unroll
    for (int mt = 0; mt < 4; mt++) {
        const int rbase = (wid * 4 + mt) * 16;
        // Row of tap k = rbase + 1 + k  (r = t - (tile0-8), t = T0+k-7)
        const uint32_t ab = a_base + (uint32_t)((rbase + 1) * 48);

        // Preload ALL 23 blocks (1-row stride) before any MMA.
        uint32_t blk[23][2];
#pragma unroll
        for (int s = 0; s < 23; s++) ldmat2(blk[s][0], blk[s][1], ab + s * 48);

        // 4 independent accumulator chains (taps mod 4).
        float acc[4][4];
#pragma unroll
        for (int c = 0; c < 4; c++)
#pragma unroll
            for (int i = 0; i < 4; i++) acc[c][i] = 0.0f;

#pragma unroll
        for (int tap = 0; tap < KK; tap++) {
            const int c = tap & 3;
            mma16816(acc[c][0], acc[c][1], acc[c][2], acc[c][3],
                     blk[tap][0], blk[tap + 8][0], blk[tap][1], blk[tap + 8][1],
                     bh0[tap], bh1[tap]);
        }

        const float d0 = acc[0][0] + acc[1][0] + acc[2][0] + acc[3][0];
        const float d1 = acc[0][1] + acc[1][1] + acc[2][1] + acc[3][1];
        const float d2 = acc[0][2] + acc[1][2] + acc[2][2] + acc[3][2];
        const float d3 = acc[0][3] + acc[1][3] + acc[2][3] + acc[3][3];

        // D mapping: d0=(row gid, n=2tig), d1=(gid, 2tig+1),
        //            d2=(gid+8, 2tig), d3=(gid+8, 2tig+1)
        const int tr = tile0 + rbase + gid;
        if (2 * tig < ow) {
            float* p = ob + (size_t)(o0 + 2 * tig) * TLEN;
            p[tr]     = d0 + bias0;
            p[tr + 8] = d2 + bias0;
        }
        if (2 * tig + 1 < ow) {
            float* p = ob + (size_t)(o0 + 2 * tig + 1) * TLEN;
            p[tr]     = d1 + bias1;
            p[tr + 8] = d3 + bias1;
        }
    }
}

extern "C" void kernel_launch(void* const* d_in, const int* in_sizes, int n_in,
                              void* d_out, int out_size)
{
    (void)in_sizes; (void)n_in; (void)out_size;
    const float* x    = (const float*)d_in[0];
    const float* w    = (const float*)d_in[1];
    const float* bias = (const float*)d_in[2];
    const float* mask = (const float*)d_in[3];
    float* out = (float*)d_out;

    dim3 grid(TLEN / CTAT, 26, NB);
    skel_hmma5_kernel<<<grid, TPB>>>(x, w, bias, mask, out);
}